// round 6
// baseline (speedup 1.0000x reference)
#include <cuda_runtime.h>
#include <cuda_bf16.h>
#include <cstdint>

// Quantized int8 3x3 VALID conv, hybrid tensor+fma implicit GEMM.
// Taps 0..7 on mma.sync s8 (8x m16n8k32 per 16-px tile = legacy-IMMA floor),
// tap 8 and its window-sum term on the fma pipe (dp4a), overlapping the
// tensor unit. Exact integer math throughout.
//
// x: [64,16,256,256] int32 (int8 values), w: [16,16,3,3] int32, bias: [16] f32
// out: [64,16,254,254] f32
// out = 1e-4*( Sum x*w - 3*Wsum(x) - 7*Sum(w) + 21*144 ) + bq[co]

#define CIN 16
#define COUT 16
#define HIN 256
#define WIN 256
#define HOUT 254
#define WOUT 254
#define TH 16
#define TW 64
#define ROWS 18
#define COLS 68
#define NQUADS (4 * ROWS * 17)

// B fragments for taps 0..7: mma j covers taps (2j, 2j+1) as k rows 0-15/16-31.
__device__ unsigned g_bfrag[2][4][2][32];  // [group][mma j][reg h][lane]
__device__ unsigned g_w8[COUT][4];         // tap-8 weights, packed 4 cin/word
__device__ int   g_wc[COUT];               // -7*Sum(w) + 21*144
__device__ float g_bq[COUT];

__global__ void prep_kernel(const int* __restrict__ w, const float* __restrict__ bias) {
    int t = threadIdx.x;
    if (t < 512) {
        int lane = t & 31;
        int rem  = t >> 5;          // 0..15
        int g = rem >> 3;           // group
        int j = (rem >> 1) & 3;     // mma index
        int h = rem & 1;            // b-reg
        int tap = 2 * j + h;
        int co = g * 8 + (lane >> 2);
        int cb = (lane & 3) << 2;
        unsigned pk = 0;
        #pragma unroll
        for (int i = 0; i < 4; i++)
            pk |= (unsigned)(w[(co * CIN + cb + i) * 9 + tap] & 0xFF) << (8 * i);
        g_bfrag[g][j][h][lane] = pk;
    }
    if (t < 64) {                   // tap-8 weight words
        int co = t >> 2, wi = t & 3;
        unsigned pk = 0;
        #pragma unroll
        for (int i = 0; i < 4; i++)
            pk |= (unsigned)(w[(co * CIN + 4 * wi + i) * 9 + 8] & 0xFF) << (8 * i);
        g_w8[co][wi] = pk;
    }
    if (t < COUT) {
        int s = 0;
        #pragma unroll 4
        for (int k = 0; k < CIN * 9; k++) s += w[t * CIN * 9 + k];
        g_wc[t] = -7 * s + 21 * CIN * 9;
        float b = bias[t];
        float r = rintf(b / 0.0001f);
        r = fminf(fmaxf(r, -2147483648.0f), 2147483647.0f);
        g_bq[t] = r * 0.0001f;
    }
}

__device__ __forceinline__ unsigned pack4(int a, int b, int c, int d) {
    unsigned t = __byte_perm((unsigned)a, (unsigned)b, 0x0040);
    unsigned u = __byte_perm((unsigned)c, (unsigned)d, 0x4000);
    return __byte_perm(t, u, 0x7610);
}
__device__ __forceinline__ void ldm4(unsigned a[4], unsigned addr) {
    asm volatile("ldmatrix.sync.aligned.m8n8.x4.shared.b16 {%0,%1,%2,%3},[%4];"
                 : "=r"(a[0]), "=r"(a[1]), "=r"(a[2]), "=r"(a[3]) : "r"(addr));
}
__device__ __forceinline__ void mma32(int c[4], const unsigned a[4], unsigned b0, unsigned b1) {
    asm volatile("mma.sync.aligned.m16n8k32.row.col.s32.s8.s8.s32 "
                 "{%0,%1,%2,%3},{%4,%5,%6,%7},{%8,%9},{%0,%1,%2,%3};"
                 : "+r"(c[0]), "+r"(c[1]), "+r"(c[2]), "+r"(c[3])
                 : "r"(a[0]), "r"(a[1]), "r"(a[2]), "r"(a[3]), "r"(b0), "r"(b1));
}
__device__ __forceinline__ int dot8(uint4 x, const unsigned wr[4]) {
    int s = __dp4a((int)x.x, (int)wr[0], 0);
    s = __dp4a((int)x.y, (int)wr[1], s);
    s = __dp4a((int)x.z, (int)wr[2], s);
    s = __dp4a((int)x.w, (int)wr[3], s);
    return s;
}
__device__ __forceinline__ int sum16(uint4 x) {
    int s = __dp4a((int)x.x, 0x01010101, 0);
    s = __dp4a((int)x.y, 0x01010101, s);
    s = __dp4a((int)x.z, 0x01010101, s);
    s = __dp4a((int)x.w, 0x01010101, s);
    return s;
}

__global__ void __launch_bounds__(256, 2)
conv_kernel(const int* __restrict__ inp, float* __restrict__ out) {
    // int8 tile, cin-contiguous: pixel (r,c) = 16 bytes at sx[(r*COLS+c)*4 ..]
    __shared__ __align__(16) unsigned sx[ROWS * COLS * 4];
    __shared__ __align__(16) unsigned sw8[COUT][4];
    __shared__ int   swc[COUT];
    __shared__ float sbq[COUT];

    const int tid  = threadIdx.x;
    const int lane = tid & 31;
    const int wid  = tid >> 5;
    const int n    = blockIdx.z;
    const int oh0  = blockIdx.y * TH;
    const int ow0  = blockIdx.x * TW;

    const int* xin = inp + (size_t)n * CIN * HIN * WIN;

    // ---- pack input tile: int32 -> int8, planes -> pixel-contiguous ----
    for (int gi = tid; gi < NQUADS; gi += 256) {
        int g   = gi / (ROWS * 17);
        int rem = gi - g * (ROWS * 17);
        int r   = rem / 17;
        int c4  = (rem - r * 17) * 4;
        int ih = oh0 + r, iw = ow0 + c4;
        unsigned p0, p1, p2, p3;
        const int* base = xin + (size_t)(4 * g) * (HIN * WIN) + ih * WIN + iw;
        if (ih < HIN && iw + 3 < WIN) {
            int4 v0 = *(const int4*)(base);
            int4 v1 = *(const int4*)(base + HIN * WIN);
            int4 v2 = *(const int4*)(base + 2 * HIN * WIN);
            int4 v3 = *(const int4*)(base + 3 * HIN * WIN);
            p0 = pack4(v0.x, v1.x, v2.x, v3.x);
            p1 = pack4(v0.y, v1.y, v2.y, v3.y);
            p2 = pack4(v0.z, v1.z, v2.z, v3.z);
            p3 = pack4(v0.w, v1.w, v2.w, v3.w);
        } else {
            unsigned t[4];
            #pragma unroll
            for (int j = 0; j < 4; j++) {
                t[j] = 0;
                if (ih < HIN && iw + j < WIN) {
                    int v0 = base[j];
                    int v1 = base[j + HIN * WIN];
                    int v2 = base[j + 2 * HIN * WIN];
                    int v3 = base[j + 3 * HIN * WIN];
                    t[j] = pack4(v0, v1, v2, v3);
                }
            }
            p0 = t[0]; p1 = t[1]; p2 = t[2]; p3 = t[3];
        }
        unsigned* dst = &sx[(r * COLS + c4) * 4 + g];
        dst[0] = p0; dst[4] = p1; dst[8] = p2; dst[12] = p3;
    }
    if (tid < 64) ((unsigned*)sw8)[tid] = ((const unsigned*)g_w8)[tid];
    if (tid < COUT) { swc[tid] = g_wc[tid]; sbq[tid] = g_bq[tid]; }

    // ---- B fragments into registers ----
    unsigned bf[2][4][2];
    #pragma unroll
    for (int g = 0; g < 2; g++)
        #pragma unroll
        for (int j = 0; j < 4; j++) {
            bf[g][j][0] = g_bfrag[g][j][0][lane];
            bf[g][j][1] = g_bfrag[g][j][1][lane];
        }
    __syncthreads();

    // Per-lane A-address tap offsets (taps 0..7 over 4 mma)
    const int hi = lane >> 4;
    unsigned toff[4];
    #pragma unroll
    for (int j = 0; j < 4; j++) {
        int t = 2 * j + hi;
        toff[j] = (unsigned)(((t / 3) * COLS + (t % 3)) * 16);
    }

    const int q    = lane & 3;
    const int prow = lane >> 2;
    const int wc0 = swc[2 * q],     wc1 = swc[2 * q + 1];
    const int wc2 = swc[8 + 2 * q], wc3 = swc[9 + 2 * q];
    const float bq0 = sbq[2 * q],     bq1 = sbq[2 * q + 1];
    const float bq2 = sbq[8 + 2 * q], bq3 = sbq[9 + 2 * q];

    // tap-8 weight words for this lane's 4 couts
    unsigned w8r0[4], w8r1[4], w8r2[4], w8r3[4];
    #pragma unroll
    for (int i = 0; i < 4; i++) {
        w8r0[i] = sw8[2 * q][i];
        w8r1[i] = sw8[2 * q + 1][i];
        w8r2[i] = sw8[8 + 2 * q][i];
        w8r3[i] = sw8[9 + 2 * q][i];
    }

    const unsigned sxa = (unsigned)__cvta_generic_to_shared(sx);
    const size_t cs = (size_t)HOUT * WOUT;
    float* obase = out + (size_t)(n * COUT) * cs;

    // ---- 64 pixel-tiles (16 px each); warp w handles tiles w, w+8, ... ----
    #pragma unroll 1
    for (int tt = wid; tt < 64; tt += 8) {
        const int r  = tt >> 2;
        const int c0 = (tt & 3) << 4;
        const unsigned tilebase = sxa + (unsigned)(((r * COLS + c0 + (lane & 15)) * 16));

        unsigned a[4][4];
        #pragma unroll
        for (int j = 0; j < 4; j++) ldm4(a[j], tilebase + toff[j]);

        int acc0[4] = {0, 0, 0, 0};
        int acc1[4] = {0, 0, 0, 0};
        #pragma unroll
        for (int j = 0; j < 4; j++) {
            mma32(acc0, a[j], bf[0][j][0], bf[0][j][1]);
            mma32(acc1, a[j], bf[1][j][0], bf[1][j][1]);
        }

        // tap-8 x vectors (all 16 cin) for this lane's two pixels
        const unsigned* t8p = &sx[(((r + 2) * COLS) + c0 + prow + 2) * 4];
        uint4 xw0 = *(const uint4*)t8p;
        uint4 xw1 = *(const uint4*)(t8p + 32);   // +8 pixels

        // window sums: taps 0..7 from A fragments (quad partials), tap 8 exact
        int s_lo = 0, s_hi = 0;
        #pragma unroll
        for (int j = 0; j < 4; j++) {
            s_lo = __dp4a((int)a[j][0], 0x01010101, s_lo);
            s_hi = __dp4a((int)a[j][1], 0x01010101, s_hi);
            s_lo = __dp4a((int)a[j][2], 0x01010101, s_lo);
            s_hi = __dp4a((int)a[j][3], 0x01010101, s_hi);
        }
        s_lo += __shfl_xor_sync(0xffffffffu, s_lo, 1);
        s_lo += __shfl_xor_sync(0xffffffffu, s_lo, 2);
        s_hi += __shfl_xor_sync(0xffffffffu, s_hi, 1);
        s_hi += __shfl_xor_sync(0xffffffffu, s_hi, 2);
        s_lo += sum16(xw0);
        s_hi += sum16(xw1);

        const int oh = oh0 + r;
        if (oh < HOUT) {
            float* ob = obase + (size_t)oh * WOUT;
            int px0 = ow0 + c0 + prow;
            int px1 = px0 + 8;
            if (px0 < WOUT) {
                ob[(size_t)(2 * q)     * cs + px0] =
                    fmaf((float)(acc0[0] + dot8(xw0, w8r0) - 3 * s_lo + wc0), 1e-4f, bq0);
                ob[(size_t)(2 * q + 1) * cs + px0] =
                    fmaf((float)(acc0[1] + dot8(xw0, w8r1) - 3 * s_lo + wc1), 1e-4f, bq1);
                ob[(size_t)(8 + 2 * q) * cs + px0] =
                    fmaf((float)(acc1[0] + dot8(xw0, w8r2) - 3 * s_lo + wc2), 1e-4f, bq2);
                ob[(size_t)(9 + 2 * q) * cs + px0] =
                    fmaf((float)(acc1[1] + dot8(xw0, w8r3) - 3 * s_lo + wc3), 1e-4f, bq3);
            }
            if (px1 < WOUT) {
                ob[(size_t)(2 * q)     * cs + px1] =
                    fmaf((float)(acc0[2] + dot8(xw1, w8r0) - 3 * s_hi + wc0), 1e-4f, bq0);
                ob[(size_t)(2 * q + 1) * cs + px1] =
                    fmaf((float)(acc0[3] + dot8(xw1, w8r1) - 3 * s_hi + wc1), 1e-4f, bq1);
                ob[(size_t)(8 + 2 * q) * cs + px1] =
                    fmaf((float)(acc1[2] + dot8(xw1, w8r2) - 3 * s_hi + wc2), 1e-4f, bq2);
                ob[(size_t)(9 + 2 * q) * cs + px1] =
                    fmaf((float)(acc1[3] + dot8(xw1, w8r3) - 3 * s_hi + wc3), 1e-4f, bq3);
            }
        }
    }
}

extern "C" void kernel_launch(void* const* d_in, const int* in_sizes, int n_in,
                              void* d_out, int out_size) {
    const int*   x    = (const int*)d_in[0];
    const int*   w    = (const int*)d_in[1];
    const float* bias = (const float*)d_in[2];
    float* outp = (float*)d_out;

    prep_kernel<<<1, 512>>>(w, bias);

    dim3 grid((WOUT + TW - 1) / TW,   // 4
              (HOUT + TH - 1) / TH,   // 16
              64);                    // batch
    conv_kernel<<<grid, 256>>>(x, outp);
}

// round 7
// speedup vs baseline: 1.1661x; 1.1661x over previous
#include <cuda_runtime.h>
#include <cuda_bf16.h>
#include <cstdint>

// Quantized int8 3x3 VALID conv, hybrid tensor+fma implicit GEMM.
// Taps 0..7 on mma.sync s8 (8x m16n8k32 per 16-px tile), tap 8 + window sum
// on the fma pipe (dp4a), 3 CTAs/SM to keep the tensor unit fed.
// Exact integer math; one final fmaf.
//
// x: [64,16,256,256] int32 (int8 values), w: [16,16,3,3] int32, bias: [16] f32
// out: [64,16,254,254] f32
// out = 1e-4*( Sum x*w - 3*Wsum(x) - 7*Sum(w) + 21*144 ) + bq[co]

#define CIN 16
#define COUT 16
#define HIN 256
#define WIN 256
#define HOUT 254
#define WOUT 254
#define TH 16
#define TW 64
#define ROWS 18
#define COLS 68
#define NQUADS (4 * ROWS * 17)

__device__ unsigned g_bfrag[2][4][2][32];  // [group][mma j][reg h][lane], taps 0..7
__device__ unsigned g_w8[COUT][4];         // tap-8 weights, 4 cin/word
__device__ int   g_wc[COUT];               // -7*Sum(w) + 21*144
__device__ float g_bq[COUT];

__global__ void prep_kernel(const int* __restrict__ w, const float* __restrict__ bias) {
    int t = threadIdx.x;
    if (t < 512) {
        int lane = t & 31;
        int rem  = t >> 5;
        int g = rem >> 3;
        int j = (rem >> 1) & 3;
        int h = rem & 1;
        int tap = 2 * j + h;
        int co = g * 8 + (lane >> 2);
        int cb = (lane & 3) << 2;
        unsigned pk = 0;
        #pragma unroll
        for (int i = 0; i < 4; i++)
            pk |= (unsigned)(w[(co * CIN + cb + i) * 9 + tap] & 0xFF) << (8 * i);
        g_bfrag[g][j][h][lane] = pk;
    }
    if (t < 64) {
        int co = t >> 2, wi = t & 3;
        unsigned pk = 0;
        #pragma unroll
        for (int i = 0; i < 4; i++)
            pk |= (unsigned)(w[(co * CIN + 4 * wi + i) * 9 + 8] & 0xFF) << (8 * i);
        g_w8[co][wi] = pk;
    }
    if (t < COUT) {
        int s = 0;
        #pragma unroll 4
        for (int k = 0; k < CIN * 9; k++) s += w[t * CIN * 9 + k];
        g_wc[t] = -7 * s + 21 * CIN * 9;
        float b = bias[t];
        float r = rintf(b / 0.0001f);
        r = fminf(fmaxf(r, -2147483648.0f), 2147483647.0f);
        g_bq[t] = r * 0.0001f;
    }
}

__device__ __forceinline__ unsigned pack4(int a, int b, int c, int d) {
    unsigned t = __byte_perm((unsigned)a, (unsigned)b, 0x0040);
    unsigned u = __byte_perm((unsigned)c, (unsigned)d, 0x4000);
    return __byte_perm(t, u, 0x7610);
}
__device__ __forceinline__ void ldm4(unsigned a[4], unsigned addr) {
    asm volatile("ldmatrix.sync.aligned.m8n8.x4.shared.b16 {%0,%1,%2,%3},[%4];"
                 : "=r"(a[0]), "=r"(a[1]), "=r"(a[2]), "=r"(a[3]) : "r"(addr));
}
__device__ __forceinline__ void mma32(int c[4], const unsigned a[4], unsigned b0, unsigned b1) {
    asm volatile("mma.sync.aligned.m16n8k32.row.col.s32.s8.s8.s32 "
                 "{%0,%1,%2,%3},{%4,%5,%6,%7},{%8,%9},{%0,%1,%2,%3};"
                 : "+r"(c[0]), "+r"(c[1]), "+r"(c[2]), "+r"(c[3])
                 : "r"(a[0]), "r"(a[1]), "r"(a[2]), "r"(a[3]), "r"(b0), "r"(b1));
}
__device__ __forceinline__ int dot8(uint4 x, uint4 w) {
    int s = __dp4a((int)x.x, (int)w.x, 0);
    s = __dp4a((int)x.y, (int)w.y, s);
    s = __dp4a((int)x.z, (int)w.z, s);
    s = __dp4a((int)x.w, (int)w.w, s);
    return s;
}
__device__ __forceinline__ int sum16(uint4 x) {
    int s = __dp4a((int)x.x, 0x01010101, 0);
    s = __dp4a((int)x.y, 0x01010101, s);
    s = __dp4a((int)x.z, 0x01010101, s);
    s = __dp4a((int)x.w, 0x01010101, s);
    return s;
}

__global__ void __launch_bounds__(256, 3)
conv_kernel(const int* __restrict__ inp, float* __restrict__ out) {
    __shared__ __align__(16) unsigned sx[ROWS * COLS * 4];   // pixel-major int8 tile
    __shared__ __align__(16) uint4 sw8[COUT];                 // tap-8 weights
    __shared__ int   swc[COUT];
    __shared__ float sbq[COUT];

    const int tid  = threadIdx.x;
    const int lane = tid & 31;
    const int wid  = tid >> 5;
    const int n    = blockIdx.z;
    const int oh0  = blockIdx.y * TH;
    const int ow0  = blockIdx.x * TW;

    const int* xin = inp + (size_t)n * CIN * HIN * WIN;

    // ---- pack input tile: int32 -> int8, planes -> pixel-contiguous ----
    for (int gi = tid; gi < NQUADS; gi += 256) {
        int g   = gi / (ROWS * 17);
        int rem = gi - g * (ROWS * 17);
        int r   = rem / 17;
        int c4  = (rem - r * 17) * 4;
        int ih = oh0 + r, iw = ow0 + c4;
        unsigned p0, p1, p2, p3;
        const int* base = xin + (size_t)(4 * g) * (HIN * WIN) + ih * WIN + iw;
        if (ih < HIN && iw + 3 < WIN) {
            int4 v0 = *(const int4*)(base);
            int4 v1 = *(const int4*)(base + HIN * WIN);
            int4 v2 = *(const int4*)(base + 2 * HIN * WIN);
            int4 v3 = *(const int4*)(base + 3 * HIN * WIN);
            p0 = pack4(v0.x, v1.x, v2.x, v3.x);
            p1 = pack4(v0.y, v1.y, v2.y, v3.y);
            p2 = pack4(v0.z, v1.z, v2.z, v3.z);
            p3 = pack4(v0.w, v1.w, v2.w, v3.w);
        } else {
            unsigned t[4];
            #pragma unroll
            for (int j = 0; j < 4; j++) {
                t[j] = 0;
                if (ih < HIN && iw + j < WIN) {
                    int v0 = base[j];
                    int v1 = base[j + HIN * WIN];
                    int v2 = base[j + 2 * HIN * WIN];
                    int v3 = base[j + 3 * HIN * WIN];
                    t[j] = pack4(v0, v1, v2, v3);
                }
            }
            p0 = t[0]; p1 = t[1]; p2 = t[2]; p3 = t[3];
        }
        unsigned* dst = &sx[(r * COLS + c4) * 4 + g];
        dst[0] = p0; dst[4] = p1; dst[8] = p2; dst[12] = p3;
    }
    if (tid < 64) ((unsigned*)sw8)[tid] = ((const unsigned*)g_w8)[tid];
    if (tid < COUT) { swc[tid] = g_wc[tid]; sbq[tid] = g_bq[tid]; }

    // ---- B fragments into registers ----
    unsigned bf[2][4][2];
    #pragma unroll
    for (int g = 0; g < 2; g++)
        #pragma unroll
        for (int j = 0; j < 4; j++) {
            bf[g][j][0] = g_bfrag[g][j][0][lane];
            bf[g][j][1] = g_bfrag[g][j][1][lane];
        }
    __syncthreads();

    const int hi = lane >> 4;
    unsigned toff[4];
    #pragma unroll
    for (int j = 0; j < 4; j++) {
        int t = 2 * j + hi;
        toff[j] = (unsigned)(((t / 3) * COLS + (t % 3)) * 16);
    }

    const int q    = lane & 3;
    const int prow = lane >> 2;
    const int co0 = 2 * q, co1 = 2 * q + 1, co2 = 8 + 2 * q, co3 = 9 + 2 * q;
    const int wc0 = swc[co0], wc1 = swc[co1], wc2 = swc[co2], wc3 = swc[co3];
    const float bq0 = sbq[co0], bq1 = sbq[co1], bq2 = sbq[co2], bq3 = sbq[co3];

    const unsigned sxa = (unsigned)__cvta_generic_to_shared(sx);
    const size_t cs = (size_t)HOUT * WOUT;
    float* obase = out + (size_t)(n * COUT) * cs;

    #pragma unroll 1
    for (int tt = wid; tt < 64; tt += 8) {
        const int r  = tt >> 2;
        const int c0 = (tt & 3) << 4;
        const unsigned tilebase = sxa + (unsigned)(((r * COLS + c0 + (lane & 15)) * 16));

        unsigned a[4][4];
        #pragma unroll
        for (int j = 0; j < 4; j++) ldm4(a[j], tilebase + toff[j]);

        int acc0[4] = {0, 0, 0, 0};
        int acc1[4] = {0, 0, 0, 0};
        #pragma unroll
        for (int j = 0; j < 4; j++) {
            mma32(acc0, a[j], bf[0][j][0], bf[0][j][1]);
            mma32(acc1, a[j], bf[1][j][0], bf[1][j][1]);
        }

        // tap-8 x vectors (all 16 cin) for this lane's two pixels
        const unsigned* t8p = &sx[(((r + 2) * COLS) + c0 + prow + 2) * 4];
        uint4 xw0 = *(const uint4*)t8p;
        uint4 xw1 = *(const uint4*)(t8p + 32);

        // window sums: taps 0..7 from A fragments, tap 8 exact
        int s_lo = 0, s_hi = 0;
        #pragma unroll
        for (int j = 0; j < 4; j++) {
            s_lo = __dp4a((int)a[j][0], 0x01010101, s_lo);
            s_hi = __dp4a((int)a[j][1], 0x01010101, s_hi);
            s_lo = __dp4a((int)a[j][2], 0x01010101, s_lo);
            s_hi = __dp4a((int)a[j][3], 0x01010101, s_hi);
        }
        s_lo += __shfl_xor_sync(0xffffffffu, s_lo, 1);
        s_lo += __shfl_xor_sync(0xffffffffu, s_lo, 2);
        s_hi += __shfl_xor_sync(0xffffffffu, s_hi, 1);
        s_hi += __shfl_xor_sync(0xffffffffu, s_hi, 2);
        s_lo += sum16(xw0);
        s_hi += sum16(xw1);

        // tap-8 weights from smem (broadcast LDS.128, conflict-free)
        uint4 w0 = sw8[co0], w1 = sw8[co1], w2 = sw8[co2], w3 = sw8[co3];

        const int oh = oh0 + r;
        if (oh < HOUT) {
            float* ob = obase + (size_t)oh * WOUT;
            int px0 = ow0 + c0 + prow;
            int px1 = px0 + 8;
            if (px0 < WOUT) {
                ob[(size_t)co0 * cs + px0] = fmaf((float)(acc0[0] + dot8(xw0, w0) - 3 * s_lo + wc0), 1e-4f, bq0);
                ob[(size_t)co1 * cs + px0] = fmaf((float)(acc0[1] + dot8(xw0, w1) - 3 * s_lo + wc1), 1e-4f, bq1);
                ob[(size_t)co2 * cs + px0] = fmaf((float)(acc1[0] + dot8(xw0, w2) - 3 * s_lo + wc2), 1e-4f, bq2);
                ob[(size_t)co3 * cs + px0] = fmaf((float)(acc1[1] + dot8(xw0, w3) - 3 * s_lo + wc3), 1e-4f, bq3);
            }
            if (px1 < WOUT) {
                ob[(size_t)co0 * cs + px1] = fmaf((float)(acc0[2] + dot8(xw1, w0) - 3 * s_hi + wc0), 1e-4f, bq0);
                ob[(size_t)co1 * cs + px1] = fmaf((float)(acc0[3] + dot8(xw1, w1) - 3 * s_hi + wc1), 1e-4f, bq1);
                ob[(size_t)co2 * cs + px1] = fmaf((float)(acc1[2] + dot8(xw1, w2) - 3 * s_hi + wc2), 1e-4f, bq2);
                ob[(size_t)co3 * cs + px1] = fmaf((float)(acc1[3] + dot8(xw1, w3) - 3 * s_hi + wc3), 1e-4f, bq3);
            }
        }
    }
}

extern "C" void kernel_launch(void* const* d_in, const int* in_sizes, int n_in,
                              void* d_out, int out_size) {
    const int*   x    = (const int*)d_in[0];
    const int*   w    = (const int*)d_in[1];
    const float* bias = (const float*)d_in[2];
    float* outp = (float*)d_out;

    prep_kernel<<<1, 512>>>(w, bias);

    dim3 grid((WOUT + TW - 1) / TW,   // 4
              (HOUT + TH - 1) / TH,   // 16
              64);                    // batch
    conv_kernel<<<grid, 256>>>(x, outp);
}